// round 5
// baseline (speedup 1.0000x reference)
#include <cuda_runtime.h>
#include <math.h>
#include <stdint.h>

#define TT 512
#define BB 32
#define DD 1024
#define NBLK 128            // scan grid; 1 block/SM, all co-resident
#define EPB 8               // e-rows of W_h per scan block
#define SCAN_THREADS 640    // 16 compute warps + 4 staging warps

typedef unsigned long long ull;

// ---------------- scratch (static device memory; no allocations) ----------------
__device__ float    g_Wx[(size_t)TT * BB * DD];     // 64 MB: x@W_x^T + b
__device__ float    g_hT[2][DD * BB];               // double-buffered h, [d][b]
__device__ unsigned g_cnt[(TT + 1) * 4];            // per-step per-quarter arrival counters

// ---------------- PTX helpers ----------------
#define FFMA2(d, a, b) asm("fma.rn.f32x2 %0, %1, %2, %0;" : "+l"(d) : "l"(a), "l"(b))

__device__ __forceinline__ uint32_t smem_u32(const void* p) {
    return (uint32_t)__cvta_generic_to_shared(p);
}
__device__ __forceinline__ void mbar_init(uint32_t a, uint32_t cnt) {
    asm volatile("mbarrier.init.shared.b64 [%0], %1;" :: "r"(a), "r"(cnt) : "memory");
}
__device__ __forceinline__ void mbar_expect_tx(uint32_t a, uint32_t bytes) {
    asm volatile("mbarrier.arrive.expect_tx.shared.b64 _, [%0], %1;" :: "r"(a), "r"(bytes) : "memory");
}
__device__ __forceinline__ void mbar_wait(uint32_t a, uint32_t parity) {
    uint32_t done;
    do {
        asm volatile(
            "{\n\t.reg .pred p;\n\t"
            "mbarrier.try_wait.parity.shared.b64 p, [%1], %2;\n\t"
            "selp.b32 %0, 1, 0, p;\n\t}"
            : "=r"(done) : "r"(a), "r"(parity) : "memory");
    } while (!done);
}
__device__ __forceinline__ void bulk_g2s(uint32_t dst, const void* src, uint32_t bytes, uint32_t mbar) {
    asm volatile("cp.async.bulk.shared::cta.global.mbarrier::complete_tx::bytes [%0], [%1], %2, [%3];"
                 :: "r"(dst), "l"(src), "r"(bytes), "r"(mbar) : "memory");
}
__device__ __forceinline__ unsigned ld_acq(const unsigned* p) {
    unsigned v;
    asm volatile("ld.acquire.gpu.global.u32 %0, [%1];" : "=r"(v) : "l"(p) : "memory");
    return v;
}

// ---------------- init: counters + transposed h0 ----------------
__global__ void init_kernel(const float* __restrict__ h0) {
    int idx = blockIdx.x * blockDim.x + threadIdx.x;   // 0..32767
    if (idx < (TT + 1) * 4) g_cnt[idx] = (idx < 4) ? 32u : 0u;   // step-0 quarters pre-armed
    if (idx < DD * BB) {
        int d = idx >> 5;
        int b = idx & 31;
        g_hT[0][idx] = h0[b * DD + d];
    }
}

// ---------------- phase 1: Wx = x @ W_x^T + b  (FFMA2 SGEMM) ----------------
// M=16384, N=1024, K=1024. 128x128 tile, BK=8, double-buffered, A stored pre-splatted.
__global__ void __launch_bounds__(256) gemm_wx_kernel(
    const float* __restrict__ x,
    const float* __restrict__ Wxw,
    const float* __restrict__ bias)
{
    __shared__ ull   As2[2][8][128];   // splatted A: both f32 halves = a[m][k]
    __shared__ float Bs [2][8][128];

    const int tid = threadIdx.x;
    const int tx = tid & 15;
    const int ty = tid >> 4;
    const int m0 = blockIdx.y * 128;
    const int n0 = blockIdx.x * 128;

    const int lrow = tid >> 1;           // 0..127
    const int lc4  = (tid & 1) * 4;      // 0 or 4

    const float* pa_src = &x  [(size_t)(m0 + lrow) * DD + lc4];
    const float* pb_src = &Wxw[(size_t)(n0 + lrow) * DD + lc4];

    ull acc2[8][4];
    #pragma unroll
    for (int i = 0; i < 8; i++)
        #pragma unroll
        for (int j = 0; j < 4; j++) acc2[i][j] = 0ull;

    float4 pa = *(const float4*)pa_src;
    float4 pb = *(const float4*)pb_src;

    #define STAGE_TILE(buf)                                                         \
        do {                                                                        \
            uint32_t ax = __float_as_uint(pa.x), ay = __float_as_uint(pa.y);        \
            uint32_t az = __float_as_uint(pa.z), aw = __float_as_uint(pa.w);        \
            As2[buf][lc4 + 0][lrow] = ((ull)ax << 32) | ax;                         \
            As2[buf][lc4 + 1][lrow] = ((ull)ay << 32) | ay;                         \
            As2[buf][lc4 + 2][lrow] = ((ull)az << 32) | az;                         \
            As2[buf][lc4 + 3][lrow] = ((ull)aw << 32) | aw;                         \
            Bs[buf][lc4 + 0][lrow] = pb.x; Bs[buf][lc4 + 1][lrow] = pb.y;           \
            Bs[buf][lc4 + 2][lrow] = pb.z; Bs[buf][lc4 + 3][lrow] = pb.w;           \
        } while (0)

    STAGE_TILE(0);
    __syncthreads();

    const int NKT = DD / 8;   // 128
    for (int kt = 0; kt < NKT; kt++) {
        int cur = kt & 1;
        if (kt + 1 < NKT) {
            pa = *(const float4*)(pa_src + (size_t)(kt + 1) * 8);
            pb = *(const float4*)(pb_src + (size_t)(kt + 1) * 8);
        }

        #pragma unroll
        for (int k = 0; k < 8; k++) {
            const ulonglong2* ap = (const ulonglong2*)&As2[cur][k][ty * 8];
            ulonglong2 av0 = ap[0], av1 = ap[1], av2 = ap[2], av3 = ap[3];
            const ulonglong2* bp = (const ulonglong2*)&Bs[cur][k][tx * 8];
            ulonglong2 b01 = bp[0], b45 = bp[1];
            ull a_[8] = {av0.x, av0.y, av1.x, av1.y, av2.x, av2.y, av3.x, av3.y};
            ull b_[4] = {b01.x, b01.y, b45.x, b45.y};
            #pragma unroll
            for (int i = 0; i < 8; i++)
                #pragma unroll
                for (int j = 0; j < 4; j++)
                    FFMA2(acc2[i][j], a_[i], b_[j]);
        }

        if (kt + 1 < NKT) {
            int nxt = cur ^ 1;
            STAGE_TILE(nxt);
            __syncthreads();
        }
    }

    float4 bi0 = *(const float4*)&bias[n0 + tx * 8];
    float4 bi1 = *(const float4*)&bias[n0 + tx * 8 + 4];
    float bb[8] = {bi0.x, bi0.y, bi0.z, bi0.w, bi1.x, bi1.y, bi1.z, bi1.w};

    #pragma unroll
    for (int i = 0; i < 8; i++) {
        float o[8];
        #pragma unroll
        for (int j = 0; j < 4; j++) {
            o[j * 2 + 0] = __uint_as_float((uint32_t)(acc2[i][j] & 0xffffffffull)) + bb[j * 2 + 0];
            o[j * 2 + 1] = __uint_as_float((uint32_t)(acc2[i][j] >> 32))          + bb[j * 2 + 1];
        }
        size_t row = (size_t)(m0 + ty * 8 + i) * DD + n0 + tx * 8;
        *(float4*)&g_Wx[row]     = make_float4(o[0], o[1], o[2], o[3]);
        *(float4*)&g_Wx[row + 4] = make_float4(o[4], o[5], o[6], o[7]);
    }
    #undef STAGE_TILE
}

// ---------------- phase 2: persistent scan ----------------
// smem layout (dynamic):
//   Ws2 : ull [8*1024]     pre-splatted W_h slice      65536 B
//   hs  : float [32768]    staged h ([d][b])          131072 B
//   red : float [16*257]   reduction buffer            16448 B
//   mbar: ull [4]                                         64 B
#define WS2_BYTES  65536
#define HS_BYTES   131072
#define RED_BYTES  16448
#define SMEM_SCAN  (WS2_BYTES + HS_BYTES + RED_BYTES + 64)

__global__ void __launch_bounds__(SCAN_THREADS, 1) scan_kernel(
    const float* __restrict__ z,
    const float* __restrict__ Wh,
    float* __restrict__ out)
{
    extern __shared__ char sm[];
    ull*   Ws2 = (ull*)sm;
    float* hs  = (float*)(sm + WS2_BYTES);
    float* red = (float*)(sm + WS2_BYTES + HS_BYTES);
    ull*   mbb = (ull*)(sm + WS2_BYTES + HS_BYTES + RED_BYTES);

    const int tid = threadIdx.x;
    const int e0  = blockIdx.x * EPB;
    const uint32_t hs_a  = smem_u32(hs);
    const uint32_t mb_a  = smem_u32(mbb);

    // build pre-splatted W_h slice
    for (int idx = tid; idx < 8 * 1024; idx += SCAN_THREADS) {
        int r = idx >> 10, c = idx & 1023;
        uint32_t w = __float_as_uint(Wh[(size_t)(e0 + r) * DD + c]);
        Ws2[idx] = ((ull)w << 32) | w;
    }
    if (tid == 0) {
        #pragma unroll
        for (int q = 0; q < 4; q++) mbar_init(mb_a + q * 8, 1);
    }
    __syncthreads();

    // roles
    const bool is_stager = (tid >= 512) && ((tid & 31) == 0);   // tids 512,544,576,608
    const int  sq        = (tid - 512) >> 5;                    // stager's quarter

    // producer mapping (tid < 512)
    const int ds  = tid >> 4;            // 0..31
    const int sid = tid & 15;
    const int eg  = sid >> 3;            // 0..1
    const int bg  = sid & 7;             // 0..7
    const int wid = tid >> 5;
    const int lane = tid & 31;

    // consumer mapping (tid < 256)
    const int cb = tid >> 3;
    const int ce = tid & 7;
    const int cslot = (tid & 255) ^ ((((tid & 255) >> 5) & 7) << 2);

    const int myq = blockIdx.x >> 5;     // which d-quarter this block produces
    const size_t OUT2 = (size_t)TT * BB * DD;

    // staging helper: wait producers of quarter q at step t (acquire), then bulk-copy
    #define STAGE_Q(q_, t_)                                                         \
        do {                                                                        \
            if ((t_) > 0) {                                                         \
                const unsigned* c = &g_cnt[(t_) * 4 + (q_)];                        \
                while (ld_acq(c) < 32u) { }                                         \
            }                                                                       \
            uint32_t mb = mb_a + (q_) * 8;                                          \
            mbar_expect_tx(mb, 32768);                                              \
            const float* src = g_hT[(t_) & 1] + (q_) * 8192;                        \
            uint32_t dst = hs_a + (q_) * 32768;                                     \
            bulk_g2s(dst,         src,        16384, mb);                           \
            bulk_g2s(dst + 16384, src + 4096, 16384, mb);                           \
        } while (0)

    if (is_stager) STAGE_Q(sq, 0);

    for (int t = 0; t < TT; t++) {
        float wx = 0.0f, zv = 0.0f;
        size_t mo = 0;
        ull acc2[4][2] = {};

        if (tid < 512) {
            if (tid < 256) {                         // prefetch (independent of h)
                mo = (size_t)(t * BB + cb) * DD + e0 + ce;
                wx = g_Wx[mo];
                zv = z[mo];
            }

            const ulonglong2* hp = (const ulonglong2*)hs;
            const ulonglong2* wp = (const ulonglong2*)Ws2;
            #pragma unroll
            for (int q = 0; q < 4; q++) {
                mbar_wait(mb_a + q * 8, (uint32_t)(t & 1));
                #pragma unroll
                for (int dp = 0; dp < 4; dp++) {
                    int d2 = q * 256 + ds * 8 + dp * 2;
                    ulonglong2 ha = hp[(d2 + 0) * 8 + bg];   // b pairs at d2
                    ulonglong2 hb = hp[(d2 + 1) * 8 + bg];   // b pairs at d2+1
                    #pragma unroll
                    for (int i = 0; i < 4; i++) {
                        ulonglong2 wv = wp[(eg * 4 + i) * 512 + (d2 >> 1)];
                        FFMA2(acc2[i][0], wv.x, ha.x);
                        FFMA2(acc2[i][1], wv.x, ha.y);
                        FFMA2(acc2[i][0], wv.y, hb.x);
                        FFMA2(acc2[i][1], wv.y, hb.y);
                    }
                }
            }

            // fold the two d-slices sharing each warp (lanes l and l+16)
            #pragma unroll
            for (int i = 0; i < 4; i++)
                #pragma unroll
                for (int j = 0; j < 2; j++) {
                    ull o = __shfl_down_sync(0xFFFFFFFFu, acc2[i][j], 16);
                    float lo = __uint_as_float((uint32_t)(acc2[i][j] & 0xffffffffull)) +
                               __uint_as_float((uint32_t)(o & 0xffffffffull));
                    float hi = __uint_as_float((uint32_t)(acc2[i][j] >> 32)) +
                               __uint_as_float((uint32_t)(o >> 32));
                    acc2[i][j] = (((ull)__float_as_uint(hi)) << 32) | (ull)__float_as_uint(lo);
                }

            if (lane < 16) {
                #pragma unroll
                for (int i = 0; i < 4; i++)
                    #pragma unroll
                    for (int j = 0; j < 2; j++) {
                        float lo = __uint_as_float((uint32_t)(acc2[i][j] & 0xffffffffull));
                        float hi = __uint_as_float((uint32_t)(acc2[i][j] >> 32));
                        int fl0 = (bg * 4 + j * 2 + 0) * 8 + eg * 4 + i;
                        int fl1 = (bg * 4 + j * 2 + 1) * 8 + eg * 4 + i;
                        red[wid * 257 + (fl0 ^ (((fl0 >> 5) & 7) << 2))] = lo;
                        red[wid * 257 + (fl1 ^ (((fl1 >> 5) & 7) << 2))] = hi;
                    }
            }
        }
        __syncthreads();    // red complete AND hs fully consumed

        if (tid < 256) {
            float s = 0.0f;
            #pragma unroll
            for (int r = 0; r < 16; r++) s += red[r * 257 + cslot];

            float pre = s + wx;
            float hn  = tanhf(pre);
            float sig = 1.0f / (1.0f + __expf(-zv));
            float ov  = hn * (zv * sig);

            out[mo]        = hn;
            out[OUT2 + mo] = ov;
            g_hT[(t + 1) & 1][(e0 + ce) * BB + cb] = hn;
        }
        __syncthreads();    // epilogue stores done block-wide

        if (tid == 0) {     // release arrive for this block's quarter of h(t+1)
            __threadfence();
            atomicAdd(&g_cnt[(t + 1) * 4 + myq], 1u);
        }
        if (is_stager && (t + 1 < TT)) STAGE_Q(sq, t + 1);
    }
    #undef STAGE_Q
}

// ---------------- launch ----------------
extern "C" void kernel_launch(void* const* d_in, const int* in_sizes, int n_in,
                              void* d_out, int out_size) {
    const float* x    = (const float*)d_in[0];   // [T,B,D]
    const float* z    = (const float*)d_in[1];   // [T,B,D]
    const float* h0   = (const float*)d_in[2];   // [B,D]
    const float* Wxw  = (const float*)d_in[3];   // [D,D]
    const float* Whw  = (const float*)d_in[4];   // [D,D]
    const float* bias = (const float*)d_in[5];   // [D]
    float* out = (float*)d_out;                  // [2,T,B,D]

    cudaFuncSetAttribute(scan_kernel, cudaFuncAttributeMaxDynamicSharedMemorySize, SMEM_SCAN);

    init_kernel<<<128, 256>>>(h0);
    gemm_wx_kernel<<<dim3(DD / 128, (TT * BB) / 128), 256>>>(x, Wxw, bias);
    scan_kernel<<<NBLK, SCAN_THREADS, SMEM_SCAN>>>(z, Whw, out);
}